// round 12
// baseline (speedup 1.0000x reference)
#include <cuda_runtime.h>
#include <cuda_bf16.h>
#include <cstdint>

// Problem constants
#define S_      128      // seq_len
#define NBITS   256      // bits per token / neurons per head (B)
#define NHEAD   16       // heads (H)
#define NB_     12       // bits per neuron (LUT address width)
#define LUTW    128      // 2^12 / 32 words
#define HEADIN  519      // 2*B + PB
#define NSLOT   4        // heads processed concurrently per CTA
#define THREADS 512      // NSLOT * 128

// ============================================================================
// Single fused kernel. grid = 256 (one CTA per neuron column n), block = 512.
// Thread t: slot g = t>>7 (one of 4 concurrent heads), row i = t&127.
//   addr(i,j) = aq[i] | ak[j] | ap[i-j]   (each of the 12 wired connections
//   reads q (i-dep), k (j-dep), or rel-pos (i-j dep) -> disjoint bit positions)
//   parity(h,n,i) = XOR_{j<=i} sign_bit(memory[h][n][addr(i,j)])
//   out[i][n] = (#heads with parity 1) > 8     -- written as FLOAT 1.0f/0.0f
// Input pointers are identified ON DEVICE by content signature (Stage 0).
// ============================================================================
__global__ void __launch_bounds__(THREADS)
softram_fused_k(const void* __restrict__ p0,
                const void* __restrict__ p1,
                const void* __restrict__ p2,
                float* __restrict__ out)
{
    __shared__ uint32_t s_tok[8 * S_];          // 4 KB token bitset: [w][i] bit l = tokens[i][32w+l]
    __shared__ uint32_t s_lut[NSLOT][LUTW];     // 2 KB: per-slot LUT sign bits
    __shared__ uint32_t s_ak [NSLOT][S_];       // per-slot key-j address contribution
    __shared__ uint32_t s_ap [NSLOT][S_];       // per-slot distance-d address contribution
    __shared__ uint32_t s_cnt[NSLOT][S_];       // per-slot head-parity counts
    __shared__ int      s_role[3];              // content classification of p0/p1/p2

    const int n    = blockIdx.x;                // neuron column 0..255
    const int t    = threadIdx.x;
    const int lane = t & 31;
    const int wrp  = t >> 5;                    // 0..15
    const int g    = t >> 7;                    // head slot 0..3
    const int i    = t & 127;                   // query row (also plays j / d in setup)
    const int wl   = wrp & 3;                   // warp index within slot

    // ---- Stage 0: classify the three input buffers by content ----
    // tokens: first 256 ints all in {0,1}. conn: all in [0,519), some > 1.
    // memory: float bit patterns (as int: huge magnitude / negative). All
    // buffers have >= 32768 elements, so reading 256 ints is always safe.
    if (wrp < 3) {
        const int* ip = (wrp == 0) ? (const int*)p0 : (wrp == 1) ? (const int*)p1 : (const int*)p2;
        bool bin = true, rng = true;
#pragma unroll
        for (int e = 0; e < 8; e++) {
            int v = ip[e * 32 + lane];
            bin = bin && (v == 0 || v == 1);
            rng = rng && (v >= 0 && v < HEADIN);
        }
        unsigned bb = __ballot_sync(0xffffffffu, bin);
        unsigned rb = __ballot_sync(0xffffffffu, rng);
        if (lane == 0)
            s_role[wrp] = (bb == 0xffffffffu) ? 0 : (rb == 0xffffffffu) ? 1 : 2;  // 0=tok,1=conn,2=mem
    }
    __syncthreads();

    int r0 = s_role[0], r1 = s_role[1], r2 = s_role[2];
    int ti = 0, ci = 2, mi = 1;                          // positional fallback (dict order)
    if ((((1 << r0) | (1 << r1) | (1 << r2)) & 7) == 7) { // valid permutation
        ti = (r0 == 0) ? 0 : (r1 == 0) ? 1 : 2;
        ci = (r0 == 1) ? 0 : (r1 == 1) ? 1 : 2;
        mi = (r0 == 2) ? 0 : (r1 == 2) ? 1 : 2;
    }
    const int*   tokens = (ti == 0) ? (const int*)p0   : (ti == 1) ? (const int*)p1   : (const int*)p2;
    const int*   conn   = (ci == 0) ? (const int*)p0   : (ci == 1) ? (const int*)p1   : (const int*)p2;
    const float* mem    = (mi == 0) ? (const float*)p0 : (mi == 1) ? (const float*)p1 : (const float*)p2;

    // ---- Stage A: pack tokens into shared bitset (all 16 warps) ----
    // word m: token tk = m>>3, window w = m&7; warp reads 32 consecutive ints (128B coalesced)
    for (int m = wrp; m < 1024; m += 16) {
        int tk = m >> 3, w = m & 7;
        int v = tokens[tk * NBITS + w * 32 + lane];
        uint32_t b = __ballot_sync(0xffffffffu, v != 0);
        if (lane == 0) s_tok[w * S_ + tk] = b;
    }
    __syncthreads();

    uint32_t cnt = 0;

#pragma unroll 1
    for (int hh = 0; hh < NHEAD / NSLOT; hh++) {
        const int h  = hh * NSLOT + g;
        const int hn = h * NBITS + n;

        // ---- Stage B: binarize this head's 4096-float LUT slice (slot's 4 warps) ----
        const float* mb = mem + (size_t)hn * 4096;
#pragma unroll
        for (int m = wl; m < LUTW; m += 4) {
            float v = mb[m * 32 + lane];                   // 128B coalesced
            uint32_t b = __ballot_sync(0xffffffffu, v > 0.0f);
            if (lane == 0) s_lut[g][m] = b;
        }

        // ---- Stage C: split the 12 wired connections (uniform per slot) ----
        uint32_t aq = 0, ak = 0, ap = 0;
        bool anyp = false;
#pragma unroll
        for (int b = 0; b < NB_; b++) {
            int c = conn[hn * NB_ + b];                    // uniform load
            if (c < NBITS) {                               // query bit: tokens[i][c]
                aq |= ((s_tok[(c >> 5) * S_ + i] >> (c & 31)) & 1u) << b;
            } else if (c < 2 * NBITS) {                    // key bit: tokens[j][c-256] (i plays j)
                int c2 = c - NBITS;
                ak |= ((s_tok[(c2 >> 5) * S_ + i] >> (c2 & 31)) & 1u) << b;
            } else {                                       // rel-pos bit p=c-512: ((i-j)>>p)&1 (i plays d)
                ap |= (((uint32_t)i >> (c - 2 * NBITS)) & 1u) << b;
                anyp = true;
            }
        }
        s_ak[g][i] = ak;
        s_ap[g][i] = ap;
        __syncthreads();

        // ---- Stage D: causal XOR-parity scan over keys j <= i ----
        uint32_t acc = 0;
        if (anyp) {
            // ~15% of neurons wire a position bit: 3 LDS/iter
#pragma unroll 4
            for (int j = 0; j <= i; j++) {
                uint32_t a = aq | s_ak[g][j] | s_ap[g][i - j];  // broadcast + stride-1
                acc ^= s_lut[g][a >> 5] >> (a & 31u);           // random word (~3-way conflicts)
            }
        } else {
            // ~85% fast path: 2 LDS/iter
#pragma unroll 4
            for (int j = 0; j <= i; j++) {
                uint32_t a = aq | s_ak[g][j];
                acc ^= s_lut[g][a >> 5] >> (a & 31u);
            }
        }
        cnt += acc & 1u;
        __syncthreads();   // protect s_lut/s_ak/s_ap before next head round
    }

    // ---- Stage E: majority vote across the 4 slots (each holds 4 heads' parities) ----
    s_cnt[g][i] = cnt;
    __syncthreads();
    if (g == 0) {
        int s = (int)(s_cnt[0][i] + s_cnt[1][i] + s_cnt[2][i] + s_cnt[3][i]);
        // KEY CHANGE: output buffer dtype is float32 -> write 1.0f / 0.0f
        // (previous rounds wrote int 1/0, which reads as a denormal ~= 0.0f,
        //  producing the observed rel_err of exactly 1.000000)
        out[i * NBITS + n] = (s > (NHEAD / 2)) ? 1.0f : 0.0f;
    }
}

// ---------------- launch ----------------
extern "C" void kernel_launch(void* const* d_in, const int* in_sizes, int n_in,
                              void* d_out, int out_size) {
    // Pass the first three input pointers through; the kernel identifies their
    // roles by content (Stage 0). Host-side size hints only pre-order them when
    // they match known element/byte counts (harmless belt-and-suspenders).
    const void* p0 = d_in[0];
    const void* p1 = (n_in > 1) ? d_in[1] : d_in[0];
    const void* p2 = (n_in > 2) ? d_in[2] : d_in[0];
    for (int k = 0; k < n_in && k < 8; k++) {
        long long sz = (long long)in_sizes[k];
        if      (sz == 32768LL    || sz == 131072LL)   p0 = d_in[k];  // tokens
        else if (sz == 16777216LL || sz == 67108864LL) p1 = d_in[k];  // memory
        else if (sz == 49152LL    || sz == 196608LL)   p2 = d_in[k];  // connections
    }

    softram_fused_k<<<NBITS, THREADS>>>(p0, p1, p2, (float*)d_out);
    (void)out_size;
}

// round 13
// speedup vs baseline: 1.2996x; 1.2996x over previous
#include <cuda_runtime.h>
#include <cuda_bf16.h>
#include <cstdint>

// Problem constants
#define S_      128      // seq_len
#define NBITS   256      // bits per token / neurons per head (B)
#define NHEAD   16       // heads (H)
#define NB_     12       // bits per neuron (LUT address width)
#define LUTW    128      // 2^12 / 32 words
#define HEADIN  519      // 2*B + PB
#define NSLOT   4        // heads processed concurrently per CTA
#define THREADS 512      // NSLOT * 128

// ---------------- scratch (__device__ globals; no allocation) ----------------
__device__ uint32_t      g_tokbits[8 * S_];                   // 4 KB packed tokens: [w][i] bit l = tokens[i][32w+l]
__device__ unsigned char g_par[NHEAD * NBITS * S_];           // 512 KB: parity per (h, n, i); fully overwritten each launch

// ============================================================================
// Kernel 0: pack tokens + classify inputs on device is no longer needed for
// pointers (size-hint host path proved right in R12), but keep the content
// classification OUT and rely on the same host identification that passed.
// grid = 8 (window w), block = 128 (token i): thread packs one 128B line.
// ============================================================================
__global__ void pack_tokens_k(const int* __restrict__ tokens) {
    const int w = blockIdx.x;       // 0..7
    const int i = threadIdx.x;      // 0..127
    const int* p = tokens + i * NBITS + w * 32;
    uint32_t m = 0;
#pragma unroll
    for (int l = 0; l < 32; l++)
        m |= (p[l] != 0 ? 1u : 0u) << l;
    g_tokbits[w * S_ + i] = m;
}

// ============================================================================
// Kernel 1: main. grid = 1024 = (hg 0..3) x (n 0..255); block = 512 = 4 slots
// of 128 threads. Slot g handles head h = hg*4+g; thread row i = t&127.
//   addr(i,j) = aq[i] | ak[j] | ap[i-j]  (disjoint bit positions)
//   g_par[h][n][i] = XOR_{j<=i} sign_bit(memory[h][n][addr(i,j)])
// ONE head-round per CTA; slots decoupled via named barriers (no block sync
// after token staging) -> no convoy, 4x grid for ~80% occupancy.
// ============================================================================
__global__ void __launch_bounds__(THREADS, 4)
softram_main_k(const float* __restrict__ mem, const int* __restrict__ conn) {
    __shared__ uint32_t s_tok[8 * S_];          // 4 KB token bitset
    __shared__ uint32_t s_lut[NSLOT][LUTW];     // 2 KB per-slot LUT sign bits
    __shared__ uint32_t s_ak [NSLOT][S_];       // per-slot key-j contribution
    __shared__ uint32_t s_ap [NSLOT][S_];       // per-slot distance-d contribution

    const int bid  = blockIdx.x;
    const int n    = bid & (NBITS - 1);         // 0..255
    const int hg   = bid >> 8;                  // 0..3
    const int t    = threadIdx.x;
    const int lane = t & 31;
    const int wrp  = t >> 5;                    // 0..15
    const int g    = t >> 7;                    // slot 0..3
    const int i    = t & 127;                   // query row (plays j / d in setup)
    const int wl   = wrp & 3;                   // warp index within slot

    const int h  = hg * NSLOT + g;              // this slot's head
    const int hn = h * NBITS + n;

    // ---- Stage A: stage packed tokens (2 words/thread), block sync once ----
    s_tok[t]       = g_tokbits[t];
    s_tok[t + 512] = g_tokbits[t + 512];
    __syncthreads();

    // ---- Stage B: binarize this head's 4096-float LUT slice (slot's 4 warps) ----
    {
        const float* mb = mem + (size_t)hn * 4096;
#pragma unroll
        for (int m = wl; m < LUTW; m += 4) {
            float v = mb[m * 32 + lane];                   // 128B coalesced per warp
            uint32_t b = __ballot_sync(0xffffffffu, v > 0.0f);
            if (lane == 0) s_lut[g][m] = b;
        }
    }

    // ---- Stage C: split the 12 wired connections (uniform within slot) ----
    uint32_t aq = 0, ak = 0, ap = 0;
    bool anyp = false;
#pragma unroll
    for (int b = 0; b < NB_; b++) {
        int c = conn[hn * NB_ + b];                        // uniform load
        if (c < NBITS) {                                   // query bit: tokens[i][c]
            aq |= ((s_tok[(c >> 5) * S_ + i] >> (c & 31)) & 1u) << b;
        } else if (c < 2 * NBITS) {                        // key bit: tokens[j][c-256] (i plays j)
            int c2 = c - NBITS;
            ak |= ((s_tok[(c2 >> 5) * S_ + i] >> (c2 & 31)) & 1u) << b;
        } else {                                           // rel-pos bit p=c-512: ((i-j)>>p)&1 (i plays d)
            ap |= (((uint32_t)i >> (c - 2 * NBITS)) & 1u) << b;
            anyp = true;
        }
    }
    s_ak[g][i] = ak;
    s_ap[g][i] = ap;

    // Per-slot barrier only: slot's 128 threads (ids 1..4, count 128)
    asm volatile("bar.sync %0, 128;" :: "r"(g + 1) : "memory");

    // ---- Stage D: causal XOR-parity scan over keys j <= i ----
    uint32_t acc = 0;
    if (anyp) {
        // ~15% of neurons wire a position bit: 3 LDS/iter
#pragma unroll 4
        for (int j = 0; j <= i; j++) {
            uint32_t a = aq | s_ak[g][j] | s_ap[g][i - j]; // broadcast + stride-1
            acc ^= s_lut[g][a >> 5] >> (a & 31u);
        }
    } else {
        // ~85% fast path: 2 LDS/iter, unroll 8 for MLP
#pragma unroll 8
        for (int j = 0; j <= i; j++) {
            uint32_t a = aq | s_ak[g][j];
            acc ^= s_lut[g][a >> 5] >> (a & 31u);
        }
    }

    // Independent per-slot store; no post-loop sync needed anywhere.
    g_par[hn * S_ + i] = (unsigned char)(acc & 1u);        // coalesced 128B per slot
}

// ============================================================================
// Kernel 2: majority vote across 16 heads. grid = 256 (n), block = 128 (i).
// Reads coalesce over i for each head plane; scattered float stores (1 MB eff).
// ============================================================================
__global__ void reduce_heads_k(float* __restrict__ out) {
    const int n = blockIdx.x;
    const int i = threadIdx.x;
    int s = 0;
#pragma unroll
    for (int h = 0; h < NHEAD; h++)
        s += (int)g_par[(h * NBITS + n) * S_ + i];
    out[i * NBITS + n] = (s > (NHEAD / 2)) ? 1.0f : 0.0f;  // float32 output (R12 lesson)
}

// ---------------- launch ----------------
extern "C" void kernel_launch(void* const* d_in, const int* in_sizes, int n_in,
                              void* d_out, int out_size) {
    // Identification that passed in R12: exact sizes (elements or bytes) over all
    // inputs, positional fallback in setup_inputs dict order.
    const int*   tokens = (const int*)d_in[0];
    const float* memory = (n_in > 1) ? (const float*)d_in[1] : (const float*)d_in[0];
    const int*   conn   = (n_in > 2) ? (const int*)d_in[2]   : (const int*)d_in[0];
    for (int k = 0; k < n_in && k < 8; k++) {
        long long sz = (long long)in_sizes[k];
        if      (sz == 32768LL    || sz == 131072LL)   tokens = (const int*)d_in[k];
        else if (sz == 16777216LL || sz == 67108864LL) memory = (const float*)d_in[k];
        else if (sz == 49152LL    || sz == 196608LL)   conn   = (const int*)d_in[k];
    }

    pack_tokens_k  <<<8, 128>>>(tokens);
    softram_main_k <<<NSLOT * NBITS, THREADS>>>(memory, conn);   // 1024 CTAs
    reduce_heads_k <<<NBITS, S_>>>((float*)d_out);
    (void)out_size;
}

// round 14
// speedup vs baseline: 1.3651x; 1.0505x over previous
#include <cuda_runtime.h>
#include <cuda_bf16.h>
#include <cstdint>

// Problem constants
#define S_      128      // seq_len
#define NBITS   256      // bits per token / neurons per head (B)
#define NHEAD   16       // heads (H)
#define NB_     12       // bits per neuron (LUT address width)
#define LUTW    128      // 2^12 / 32 words
#define NSLOT   4        // heads processed concurrently per CTA
#define THREADS 512      // NSLOT * 128

// ---------------- scratch (__device__ globals; no allocation) ----------------
__device__ uint32_t g_tokbits[8 * S_];      // 4 KB packed tokens: [w][i] bit l = tokens[i][32w+l]
__device__ int      g_cnt[NBITS * S_];      // 128 KB: per-(n,i) head-parity counts (self-cleaned each launch)
__device__ int      g_tick[NBITS];          // per-column CTA arrival tickets (self-cleaned)

// ============================================================================
// Kernel 0: pack tokens via ballot. grid=32 x block=256 -> 256 warps, 4 words each.
// word m (0..1023): token tk=m>>3, window w=m&7; warp reads 32 consecutive ints.
// ============================================================================
__global__ void pack_tokens_k(const int* __restrict__ tokens) {
    const int lane = threadIdx.x & 31;
    const int gw   = blockIdx.x * 8 + (threadIdx.x >> 5);   // global warp 0..255
#pragma unroll
    for (int k = 0; k < 4; k++) {
        int m  = gw * 4 + k;                                // 0..1023
        int tk = m >> 3, w = m & 7;
        int v = tokens[tk * NBITS + w * 32 + lane];         // 128B coalesced
        uint32_t b = __ballot_sync(0xffffffffu, v != 0);
        if (lane == 0) g_tokbits[w * S_ + tk] = b;
    }
}

// ============================================================================
// Kernel 1: main + fused vote. grid = 1024 = (hg 0..3) x (n 0..255);
// block = 512 = 4 slots x 128 threads. Slot g -> head h = hg*4+g; thread row i.
//   addr(i,j) = aq[i] | ak[j] | ap[i-j]   (disjoint bit positions)
//   parity(h,n,i) = XOR_{j<=i} sign_bit(memory[h][n][addr(i,j)])
// Epilogue: 4 CTAs per column accumulate parity counts via L2 atomics; the
// last-arriving CTA writes out[i][n] = (count > 8) and resets the scratch.
// ============================================================================
__global__ void __launch_bounds__(THREADS, 4)
softram_main_k(const float* __restrict__ mem, const int* __restrict__ conn,
               float* __restrict__ out) {
    __shared__ uint32_t s_tok[8 * S_];                      // 4 KB token bitset
    __shared__ uint32_t s_lut[NSLOT][LUTW];                 // 2 KB per-slot LUT sign bits
    __shared__ __align__(8) uint32_t s_ak[NSLOT][S_];       // key-j contribution (uint2-loadable)
    __shared__ uint32_t s_ap [NSLOT][S_];                   // distance-d contribution
    __shared__ uint32_t s_cnt[NSLOT][S_];                   // per-slot parity bits
    __shared__ int      s_last;

    const int bid  = blockIdx.x;
    const int n    = bid & (NBITS - 1);                     // 0..255
    const int hg   = bid >> 8;                              // 0..3
    const int t    = threadIdx.x;
    const int lane = t & 31;
    const int g    = t >> 7;                                // slot 0..3
    const int i    = t & 127;                               // query row (plays j / d in setup)
    const int wl   = (t >> 5) & 3;                          // warp index within slot

    const int h  = hg * NSLOT + g;
    const int hn = h * NBITS + n;

    // ---- Stage A: stage packed tokens (2 words/thread) ----
    s_tok[t]       = g_tokbits[t];
    s_tok[t + 512] = g_tokbits[t + 512];
    __syncthreads();

    // ---- Stage B: binarize this head's 4096-float LUT slice (slot's 4 warps) ----
    {
        const float* mb = mem + (size_t)hn * 4096;
#pragma unroll
        for (int m = wl; m < LUTW; m += 4) {
            float v = mb[m * 32 + lane];                    // 128B coalesced per warp
            uint32_t b = __ballot_sync(0xffffffffu, v > 0.0f);
            if (lane == 0) s_lut[g][m] = b;
        }
    }

    // ---- Stage C: split the 12 wired connections (uniform within slot) ----
    uint32_t aq = 0, ak = 0, ap = 0;
    bool anyp = false;
#pragma unroll
    for (int b = 0; b < NB_; b++) {
        int c = conn[hn * NB_ + b];                         // uniform load
        if (c < NBITS) {                                    // query bit: tokens[i][c]
            aq |= ((s_tok[(c >> 5) * S_ + i] >> (c & 31)) & 1u) << b;
        } else if (c < 2 * NBITS) {                         // key bit: tokens[j][c-256] (i plays j)
            int c2 = c - NBITS;
            ak |= ((s_tok[(c2 >> 5) * S_ + i] >> (c2 & 31)) & 1u) << b;
        } else {                                            // rel-pos bit p=c-512: ((i-j)>>p)&1 (i plays d)
            ap |= (((uint32_t)i >> (c - 2 * NBITS)) & 1u) << b;
            anyp = true;
        }
    }
    s_ak[g][i] = ak;
    s_ap[g][i] = ap;

    // Per-slot barrier (slot's 128 threads) — slots stay decoupled through Stage D.
    asm volatile("bar.sync %0, 128;" :: "r"(g + 1) : "memory");

    // ---- Stage D: causal XOR-parity scan over keys j <= i ----
    uint32_t acc = 0, acc2 = 0;
    if (anyp) {
        // ~15% of neurons wire a position bit: 3 LDS/iter
#pragma unroll 4
        for (int j = 0; j <= i; j++) {
            uint32_t a = aq | s_ak[g][j] | s_ap[g][i - j];  // broadcast + stride-1
            acc ^= s_lut[g][a >> 5] >> (a & 31u);
        }
    } else {
        // ~85% fast path: uint2 over s_ak -> 1.5 LDS/iter, dual accumulators
        int j = 0;
#pragma unroll 4
        for (; j + 1 <= i; j += 2) {
            uint2 kk = *reinterpret_cast<const uint2*>(&s_ak[g][j]);
            uint32_t a0 = aq | kk.x;
            uint32_t a1 = aq | kk.y;
            acc  ^= s_lut[g][a0 >> 5] >> (a0 & 31u);
            acc2 ^= s_lut[g][a1 >> 5] >> (a1 & 31u);
        }
        if (j <= i) {
            uint32_t a = aq | s_ak[g][j];
            acc ^= s_lut[g][a >> 5] >> (a & 31u);
        }
    }
    s_cnt[g][i] = (acc ^ acc2) & 1u;

    // ---- Epilogue: fused majority vote (threadfence-reduction pattern) ----
    __syncthreads();
    if (t < S_) {
        int partial = (int)(s_cnt[0][t] + s_cnt[1][t] + s_cnt[2][t] + s_cnt[3][t]);
        atomicAdd(&g_cnt[n * S_ + t], partial);             // coalesced REDG, distinct addrs
    }
    __threadfence();
    __syncthreads();                                        // all adds fenced before ticket
    if (t == 0)
        s_last = (atomicAdd(&g_tick[n], 1) == NSLOT - 1) ? 1 : 0;
    __syncthreads();
    if (s_last && t < S_) {
        int sum = *(volatile int*)&g_cnt[n * S_ + t];       // visible: fence + ticket ordering
        out[t * NBITS + n] = (sum > (NHEAD / 2)) ? 1.0f : 0.0f;   // float32 output
        g_cnt[n * S_ + t] = 0;                              // self-clean for next launch
        if (t == 0) g_tick[n] = 0;
    }
}

// ---------------- launch ----------------
extern "C" void kernel_launch(void* const* d_in, const int* in_sizes, int n_in,
                              void* d_out, int out_size) {
    // Identification that passed R12/R13: exact sizes (elements or bytes),
    // positional fallback in setup_inputs dict order.
    const int*   tokens = (const int*)d_in[0];
    const float* memory = (n_in > 1) ? (const float*)d_in[1] : (const float*)d_in[0];
    const int*   conn   = (n_in > 2) ? (const int*)d_in[2]   : (const int*)d_in[0];
    for (int k = 0; k < n_in && k < 8; k++) {
        long long sz = (long long)in_sizes[k];
        if      (sz == 32768LL    || sz == 131072LL)   tokens = (const int*)d_in[k];
        else if (sz == 16777216LL || sz == 67108864LL) memory = (const float*)d_in[k];
        else if (sz == 49152LL    || sz == 196608LL)   conn   = (const int*)d_in[k];
    }

    pack_tokens_k  <<<32, 256>>>(tokens);
    softram_main_k <<<NSLOT * NBITS, THREADS>>>(memory, conn, (float*)d_out);
    (void)out_size;
}

// round 15
// speedup vs baseline: 1.4349x; 1.0511x over previous
#include <cuda_runtime.h>
#include <cuda_bf16.h>
#include <cstdint>

// Problem constants
#define S_      128      // seq_len
#define NBITS   256      // bits per token / neurons per head (B)
#define NHEAD   16       // heads (H)
#define NB_     12       // bits per neuron (LUT address width)
#define LUTW    128      // 2^12 / 32 words
#define NSLOT   4        // heads processed concurrently per CTA
#define THREADS 512      // NSLOT * 128
#define NUNIT   16       // CTAs-per-column * slots = 4*4 finishing units per column

// ---------------- scratch (__device__ globals; no allocation) ----------------
__device__ uint32_t g_tokbits[8 * S_];      // 4 KB packed tokens: [w][i] bit l = tokens[i][32w+l]
__device__ int      g_cnt[NBITS * S_];      // 128 KB per-(n,i) head-parity counts (self-cleaned)
__device__ int      g_tick[NBITS];          // per-column finishing tickets (self-cleaned)

// ============================================================================
// Kernel 0: pack tokens via ballot. grid=32 x 256 -> 256 warps, 4 words each.
// ============================================================================
__global__ void pack_tokens_k(const int* __restrict__ tokens) {
    const int lane = threadIdx.x & 31;
    const int gw   = blockIdx.x * 8 + (threadIdx.x >> 5);   // 0..255
#pragma unroll
    for (int k = 0; k < 4; k++) {
        int m  = gw * 4 + k;                                // 0..1023
        int tk = m >> 3, w = m & 7;
        int v = tokens[tk * NBITS + w * 32 + lane];         // 128B coalesced
        uint32_t b = __ballot_sync(0xffffffffu, v != 0);
        if (lane == 0) g_tokbits[w * S_ + tk] = b;
    }
}

// ---- parity scans over key range [j0, j1] (j0 must be even for uint2 path) ----
__device__ __forceinline__ uint32_t scan_fast(const uint32_t* __restrict__ akp,
                                              const uint32_t* __restrict__ lutp,
                                              uint32_t aq, int j0, int j1) {
    uint32_t acc = 0, acc2 = 0;
    int j = j0;
#pragma unroll 4
    for (; j + 1 <= j1; j += 2) {
        uint2 kk = *reinterpret_cast<const uint2*>(akp + j);
        uint32_t a0 = aq | kk.x, a1 = aq | kk.y;
        acc  ^= lutp[a0 >> 5] >> (a0 & 31u);
        acc2 ^= lutp[a1 >> 5] >> (a1 & 31u);
    }
    if (j <= j1) {
        uint32_t a = aq | akp[j];
        acc ^= lutp[a >> 5] >> (a & 31u);
    }
    return acc ^ acc2;
}

__device__ __forceinline__ uint32_t scan_pos(const uint32_t* __restrict__ akp,
                                             const uint32_t* __restrict__ app,
                                             const uint32_t* __restrict__ lutp,
                                             uint32_t aq, int r, int j0, int j1) {
    uint32_t acc = 0;
#pragma unroll 4
    for (int j = j0; j <= j1; j++) {
        uint32_t a = aq | akp[j] | app[r - j];
        acc ^= lutp[a >> 5] >> (a & 31u);
    }
    return acc;
}

// ============================================================================
// Kernel 1: main + slot-autonomous vote. grid = 1024 = (hg) x (n); block = 512
// = 4 independent slots of 128 threads. Slot g -> head h = hg*4+g; thread row i.
//   addr(i,j) = aq[i] | ak[j] | ap[i-j]   (disjoint bit positions)
// Balanced row-pairing: thread i<64 does row i (j=0..i) + tail of row 127-i
// (j=64..127-i) -> 65 iters; thread p>=64 does row p head (j=0..63) -> 64 iters.
// Critical path 128 -> 65 iterations; NO block-wide sync after token staging.
// ============================================================================
__global__ void __launch_bounds__(THREADS, 4)
softram_main_k(const float* __restrict__ mem, const int* __restrict__ conn,
               float* __restrict__ out) {
    __shared__ uint32_t s_tok[8 * S_];                       // 4 KB token bitset
    __shared__ uint32_t s_lut[NSLOT][LUTW];                  // 2 KB per-slot LUT bits
    __shared__ __align__(8) uint32_t s_ak[NSLOT][S_];        // key-j contribution
    __shared__ uint32_t s_ap [NSLOT][S_];                    // distance-d contribution
    __shared__ uint32_t s_ext[NSLOT][64];                    // partner-row partial parities
    __shared__ int      s_flag[NSLOT];

    const int bid  = blockIdx.x;
    const int n    = bid & (NBITS - 1);                      // 0..255
    const int hg   = bid >> 8;                               // 0..3
    const int t    = threadIdx.x;
    const int lane = t & 31;
    const int g    = t >> 7;                                 // slot 0..3
    const int i    = t & 127;                                // query row (plays j/d in setup)
    const int wl   = (t >> 5) & 3;                           // warp within slot

    const int h  = hg * NSLOT + g;
    const int hn = h * NBITS + n;

    // ---- Stage A: stage packed tokens; the only block-wide sync ----
    s_tok[t]       = g_tokbits[t];
    s_tok[t + 512] = g_tokbits[t + 512];
    __syncthreads();

    // ---- Stage B: binarize this head's 4096-float LUT slice (slot's 4 warps) ----
    {
        const float* mb = mem + (size_t)hn * 4096;
#pragma unroll
        for (int m = wl; m < LUTW; m += 4) {
            float v = mb[m * 32 + lane];                     // 128B coalesced
            uint32_t b = __ballot_sync(0xffffffffu, v > 0.0f);
            if (lane == 0) s_lut[g][m] = b;
        }
    }

    // ---- Stage C: split the 12 wired connections (uniform within slot) ----
    uint32_t aq = 0, ak = 0, ap = 0;
    bool anyp = false;
#pragma unroll
    for (int b = 0; b < NB_; b++) {
        int c = conn[hn * NB_ + b];                          // uniform load
        if (c < NBITS) {                                     // query bit: tokens[i][c]
            aq |= ((s_tok[(c >> 5) * S_ + i] >> (c & 31)) & 1u) << b;
        } else if (c < 2 * NBITS) {                          // key bit: tokens[j][c-256] (i plays j)
            int c2 = c - NBITS;
            ak |= ((s_tok[(c2 >> 5) * S_ + i] >> (c2 & 31)) & 1u) << b;
        } else {                                             // rel-pos bit p=c-512 (i plays d)
            ap |= (((uint32_t)i >> (c - 2 * NBITS)) & 1u) << b;
            anyp = true;
        }
    }
    s_ak[g][i] = ak;
    s_ap[g][i] = ap;
    asm volatile("bar.sync %0, 128;" :: "r"(g + 1) : "memory");   // slot barrier

    // ---- Stage D: balanced causal parity scan ----
    const uint32_t* lutp = s_lut[g];
    const uint32_t* akp  = s_ak[g];
    const uint32_t* app  = s_ap[g];
    const int partner = 127 - i;                             // i<64: row it helps finish
    uint32_t own;
    if (anyp) {
        if (i < 64) {
            own = scan_pos(akp, app, lutp, aq, i, 0, i);
            // partner row r=127-i shares THIS thread's aq? No: aq depends on row.
            // Recompute partner row's aq cheaply: read it from the thread that owns it?
            // aq for row r is private to thread r. Instead partner tail uses thread r's aq,
            // which we don't have -> stage aq values in shared (reuse s_ext as staging first).
            own = own; // placeholder, see below
        }
    }
    // NOTE: partner-tail needs the PARTNER ROW's aq. Stage aq into shared once:
    __shared__ uint32_t s_aq[NSLOT][S_];
    s_aq[g][i] = aq;
    asm volatile("bar.sync %0, 128;" :: "r"(g + 1) : "memory");

    uint32_t extra = 0;
    if (anyp) {
        own = scan_pos(akp, app, lutp, aq, i, 0, (i < 64) ? i : 63);
        if (i < 64)
            extra = scan_pos(akp, app, lutp, s_aq[g][partner], partner, 64, partner);
    } else {
        own = scan_fast(akp, lutp, aq, 0, (i < 64) ? i : 63);
        if (i < 64)
            extra = scan_fast(akp, lutp, s_aq[g][partner], 64, partner);
    }
    if (i < 64) s_ext[g][i] = extra;
    asm volatile("bar.sync %0, 128;" :: "r"(g + 1) : "memory");

    uint32_t parity = (i < 64) ? (own & 1u)
                               : ((own ^ s_ext[g][partner]) & 1u);  // partner = 127-i < 64

    // ---- Epilogue: slot-autonomous vote (ticket = 16 units per column) ----
    atomicAdd(&g_cnt[n * S_ + i], (int)parity);              // distinct addresses, coalesced
    __threadfence();
    asm volatile("bar.sync %0, 128;" :: "r"(g + 1) : "memory");
    if (i == 0)
        s_flag[g] = (atomicAdd(&g_tick[n], 1) == NUNIT - 1) ? 1 : 0;
    asm volatile("bar.sync %0, 128;" :: "r"(g + 1) : "memory");
    if (s_flag[g]) {                                         // exactly one slot per column
        int sum = atomicExch(&g_cnt[n * S_ + i], 0);         // read + self-clean (L2-coherent)
        out[i * NBITS + n] = (sum > (NHEAD / 2)) ? 1.0f : 0.0f;
        if (i == 0) g_tick[n] = 0;                           // self-clean ticket
    }
}

// ---------------- launch ----------------
extern "C" void kernel_launch(void* const* d_in, const int* in_sizes, int n_in,
                              void* d_out, int out_size) {
    // Identification proven in R12-R14: exact sizes (elements or bytes),
    // positional fallback in setup_inputs dict order.
    const int*   tokens = (const int*)d_in[0];
    const float* memory = (n_in > 1) ? (const float*)d_in[1] : (const float*)d_in[0];
    const int*   conn   = (n_in > 2) ? (const int*)d_in[2]   : (const int*)d_in[0];
    for (int k = 0; k < n_in && k < 8; k++) {
        long long sz = (long long)in_sizes[k];
        if      (sz == 32768LL    || sz == 131072LL)   tokens = (const int*)d_in[k];
        else if (sz == 16777216LL || sz == 67108864LL) memory = (const float*)d_in[k];
        else if (sz == 49152LL    || sz == 196608LL)   conn   = (const int*)d_in[k];
    }

    pack_tokens_k  <<<32, 256>>>(tokens);
    softram_main_k <<<NSLOT * NBITS, THREADS>>>(memory, conn, (float*)d_out);
    (void)out_size;
}